// round 9
// baseline (speedup 1.0000x reference)
#include <cuda_runtime.h>
#include <cuda_fp16.h>
#include <math.h>
#include <stdint.h>

// ---------------- problem constants ----------------
#define B_   8
#define N_   256
#define C_   3072
#define H_   8
#define HD_  384
#define FF_  12288
#define P_   32
#define NC_  (N_*C_)
#define BH_  (B_*H_)
#define QKV_SZ   (B_*N_*C_)
#define ATT_SZ   (B_*H_*N_*N_)
#define HBUF_SZ  (B_*N_*FF_)

// ---------------- device scratch ----------------
__device__ __align__(256) __half g_hq[QKV_SZ];
__device__ __align__(256) __half g_hk[QKV_SZ];
__device__ __align__(256) __half g_hvt[QKV_SZ];     // V^T: (BH, hd, N)
__device__ __align__(256) __half g_hattn2[ATT_SZ];
__device__ __align__(256) __half g_hctx[QKV_SZ];
__device__ __align__(256) __half g_hynh[QKV_SZ];
__device__ __align__(256) __half g_hh[HBUF_SZ];
__device__ __align__(256) __half g_hprojT[C_*C_];
__device__ __align__(256) __half g_hw1T[(long)C_*FF_];
__device__ __align__(256) __half g_hw2T[(long)C_*FF_];
__device__ float g_attn[ATT_SZ];
__device__ float g_y1[QKV_SZ];
__device__ float g_yn[QKV_SZ];
__device__ float g_y2[QKV_SZ];
__device__ float g_stats[B_*2];
__device__ double g_part[B_*32*2];

// ---------------- helpers ----------------
__device__ __forceinline__ float gelu_exact(float x) {
    return 0.5f * x * (1.0f + erff(x * 0.70710678118654752f));
}
__device__ __forceinline__ uint32_t smem_u32(const void* p) {
    return (uint32_t)__cvta_generic_to_shared(p);
}
__device__ __forceinline__ void cpa16(uint32_t dst, const void* src) {
    asm volatile("cp.async.cg.shared.global [%0], [%1], 16;\n" :: "r"(dst), "l"(src));
}
__device__ __forceinline__ void cp_commit() { asm volatile("cp.async.commit_group;\n"); }
template<int NN> __device__ __forceinline__ void cp_wait() {
    asm volatile("cp.async.wait_group %0;\n" :: "n"(NN));
}
__device__ __forceinline__ void ldsm_x4(uint32_t* r, uint32_t addr) {
    asm volatile("ldmatrix.sync.aligned.m8n8.x4.shared.b16 {%0,%1,%2,%3}, [%4];"
                 : "=r"(r[0]), "=r"(r[1]), "=r"(r[2]), "=r"(r[3]) : "r"(addr));
}
__device__ __forceinline__ void mma_f16(float c[4], uint32_t a0, uint32_t a1, uint32_t a2,
                                        uint32_t a3, uint32_t b0, uint32_t b1) {
    asm volatile(
        "mma.sync.aligned.m16n8k16.row.col.f32.f16.f16.f32 "
        "{%0,%1,%2,%3},{%4,%5,%6,%7},{%8,%9},{%0,%1,%2,%3};\n"
        : "+f"(c[0]), "+f"(c[1]), "+f"(c[2]), "+f"(c[3])
        : "r"(a0), "r"(a1), "r"(a2), "r"(a3), "r"(b0), "r"(b1));
}

// ================= 128x128 fp16 GEMM (attention AV) =================
#define ASZ  (128*72*2)
#define STG  (2*ASZ)
#define HSMEM (2*STG)

template<int EPI, typename OutT>
__global__ void __launch_bounds__(256, 2)
hgemm(const __half* __restrict__ A, const __half* __restrict__ Bm, OutT* __restrict__ C,
      int K, int lda, int ldb, int ldc,
      long sA, long sB, int zdiv, long sC1, long sC2,
      const float* __restrict__ bias, const float* __restrict__ resid)
{
    extern __shared__ char smem[];
    const uint32_t sbase = smem_u32(smem);

    int tid = threadIdx.x;
    int warp = tid >> 5, lane = tid & 31;
    int wm = warp >> 2, wn = warp & 3;
    int z = blockIdx.z;
    const __half* Ab = A + (long)z * sA;
    const __half* Bb = Bm + (long)z * sB;
    long coff = (long)(z / zdiv) * sC1 + (long)(z % zdiv) * sC2;
    OutT* Cb = C + coff;
    int rowBlk = blockIdx.y * 128;
    int colBlk = blockIdx.x * 128;

    float acc[4][4][4];
    #pragma unroll
    for (int mi = 0; mi < 4; mi++)
        #pragma unroll
        for (int ni = 0; ni < 4; ni++)
            #pragma unroll
            for (int r = 0; r < 4; r++) acc[mi][ni][r] = 0.0f;

    uint32_t aoff = (uint32_t)(((wm*64 + (lane & 15)) * 72 + ((lane >> 4) << 3)) * 2);
    uint32_t boff0 = (uint32_t)(((wn*32 + (lane & 7) + ((lane >> 4) << 3)) * 72 + (lane & 8)) * 2);
    uint32_t boff1 = boff0 + 16u*144u;

    auto load_chunk = [&](int ck, int s) {
        uint32_t ab = sbase + s*STG;
        uint32_t bb = ab + ASZ;
        const __half* Ag = Ab + (long)rowBlk * lda + ck*64;
        const __half* Bg = Bb + (long)colBlk * ldb + ck*64;
        #pragma unroll
        for (int it = 0; it < 4; it++) {
            int idx = tid + it*256;
            int row = idx >> 3, gq = idx & 7;
            cpa16(ab + row*144 + gq*16, Ag + (long)row*lda + gq*8);
        }
        #pragma unroll
        for (int it = 0; it < 4; it++) {
            int idx = tid + it*256;
            int row = idx >> 3, gq = idx & 7;
            cpa16(bb + row*144 + gq*16, Bg + (long)row*ldb + gq*8);
        }
        cp_commit();
    };

    int nc = K >> 6;
    load_chunk(0, 0);

    for (int c = 0; c < nc; c++) {
        int s = c & 1;
        if (c + 1 < nc) { load_chunk(c + 1, s ^ 1); cp_wait<1>(); }
        else            { cp_wait<0>(); }
        __syncthreads();

        uint32_t As = sbase + s*STG;
        uint32_t Bs = As + ASZ;
        #pragma unroll
        for (int kk = 0; kk < 64; kk += 16) {
            uint32_t a[4][4], b[2][4];
            #pragma unroll
            for (int mi = 0; mi < 4; mi++)
                ldsm_x4(a[mi], As + aoff + mi*2304u + kk*2);
            ldsm_x4(b[0], Bs + boff0 + kk*2);
            ldsm_x4(b[1], Bs + boff1 + kk*2);
            #pragma unroll
            for (int mi = 0; mi < 4; mi++)
                #pragma unroll
                for (int ni = 0; ni < 4; ni++)
                    mma_f16(acc[mi][ni], a[mi][0], a[mi][1], a[mi][2], a[mi][3],
                            b[ni >> 1][(ni & 1)*2], b[ni >> 1][(ni & 1)*2 + 1]);
        }
        __syncthreads();
    }

    int g = lane >> 2, t4 = lane & 3;
    #pragma unroll
    for (int mi = 0; mi < 4; mi++) {
        #pragma unroll
        for (int ni = 0; ni < 4; ni++) {
            int r0 = rowBlk + wm*64 + mi*16 + g;
            int c0 = colBlk + wn*32 + ni*8 + 2*t4;
            float v0 = acc[mi][ni][0], v1 = acc[mi][ni][1];
            float v2 = acc[mi][ni][2], v3 = acc[mi][ni][3];
            if (EPI == 0 || EPI == 2) {
                *(__half2*)&((__half*)Cb)[(long)r0*ldc + c0]     = __floats2half2_rn(v0, v1);
                *(__half2*)&((__half*)Cb)[(long)(r0+8)*ldc + c0] = __floats2half2_rn(v2, v3);
            } else {
                *(float2*)&((float*)Cb)[(long)r0*ldc + c0]     = make_float2(v0, v1);
                *(float2*)&((float*)Cb)[(long)(r0+8)*ldc + c0] = make_float2(v2, v3);
            }
        }
    }
}

// ================= 128x256 fp16 GEMM, 512 threads, 4-stage (QK) =================
#define A2SZ (128*144)
#define B2SZ (256*144)
#define STG2 (A2SZ + B2SZ)    // 55296
#define SMEM2 (4*STG2)        // 221184

template<int EPI, typename OutT>
__global__ void __launch_bounds__(512, 1)
hgemm256(const __half* __restrict__ A, const __half* __restrict__ Bm, OutT* __restrict__ C,
         int K, int lda, int ldb, int ldc,
         long sA, long sB, int zdiv, long sC1, long sC2,
         const float* __restrict__ bias, const float* __restrict__ resid)
{
    extern __shared__ char smem[];
    const uint32_t sbase = smem_u32(smem);

    int tid = threadIdx.x;
    int warp = tid >> 5, lane = tid & 31;
    int wm = warp >> 2, wn = warp & 3;     // 4x4 warp grid, 32x64 warp tile
    int z = blockIdx.z;
    const __half* Ab = A + (long)z * sA;
    const __half* Bb = Bm + (long)z * sB;
    long coff = (long)(z / zdiv) * sC1 + (long)(z % zdiv) * sC2;
    OutT* Cb = C + coff;
    int rowBlk = blockIdx.y * 128;
    int colBlk = blockIdx.x * 256;

    float acc[2][8][4];
    #pragma unroll
    for (int mi = 0; mi < 2; mi++)
        #pragma unroll
        for (int ni = 0; ni < 8; ni++)
            #pragma unroll
            for (int r = 0; r < 4; r++) acc[mi][ni][r] = 0.0f;

    uint32_t aoff = (uint32_t)(((wm*32 + (lane & 15)) * 72 + ((lane >> 4) << 3)) * 2);
    uint32_t boff = (uint32_t)(((wn*64 + (lane & 7) + ((lane >> 4) << 3)) * 72 + (lane & 8)) * 2);

    auto load_chunk = [&](int ck, int s) {
        uint32_t ab = sbase + s*STG2;
        uint32_t bb = ab + A2SZ;
        const __half* Ag = Ab + (long)rowBlk * lda + ck*64;
        const __half* Bg = Bb + (long)colBlk * ldb + ck*64;
        #pragma unroll
        for (int it = 0; it < 2; it++) {
            int idx = tid + it*512;
            int row = idx >> 3, gq = idx & 7;
            cpa16(ab + row*144 + gq*16, Ag + (long)row*lda + gq*8);
        }
        #pragma unroll
        for (int it = 0; it < 4; it++) {
            int idx = tid + it*512;
            int row = idx >> 3, gq = idx & 7;
            cpa16(bb + row*144 + gq*16, Bg + (long)row*ldb + gq*8);
        }
        cp_commit();
    };

    int nc = K >> 6;
    load_chunk(0, 0);
    if (nc > 1) load_chunk(1, 1); else cp_commit();
    if (nc > 2) load_chunk(2, 2); else cp_commit();

    for (int c = 0; c < nc; c++) {
        cp_wait<2>();
        __syncthreads();
        if (c + 3 < nc) load_chunk(c + 3, (c + 3) & 3);
        else            cp_commit();

        uint32_t As = sbase + (c & 3)*STG2;
        uint32_t Bs = As + A2SZ;

        uint32_t af[2][2][4], bf[2][4][4];
        #pragma unroll
        for (int mi = 0; mi < 2; mi++) ldsm_x4(af[0][mi], As + aoff + mi*2304u);
        #pragma unroll
        for (int j = 0; j < 4; j++)    ldsm_x4(bf[0][j],  Bs + boff + j*2304u);

        #pragma unroll
        for (int ki = 0; ki < 4; ki++) {
            int cur = ki & 1;
            if (ki < 3) {
                int kk2 = (ki + 1) * 16 * 2;
                #pragma unroll
                for (int mi = 0; mi < 2; mi++) ldsm_x4(af[cur^1][mi], As + aoff + mi*2304u + kk2);
                #pragma unroll
                for (int j = 0; j < 4; j++)    ldsm_x4(bf[cur^1][j],  Bs + boff + j*2304u + kk2);
            }
            #pragma unroll
            for (int mi = 0; mi < 2; mi++)
                #pragma unroll
                for (int ni = 0; ni < 8; ni++)
                    mma_f16(acc[mi][ni], af[cur][mi][0], af[cur][mi][1],
                            af[cur][mi][2], af[cur][mi][3],
                            bf[cur][ni >> 1][(ni & 1)*2], bf[cur][ni >> 1][(ni & 1)*2 + 1]);
        }
    }

    __syncthreads();
    int g = lane >> 2, t4 = lane & 3;
    #pragma unroll
    for (int mi = 0; mi < 2; mi++) {
        #pragma unroll
        for (int ni = 0; ni < 8; ni++) {
            int r0 = rowBlk + wm*32 + mi*16 + g;
            int c0 = colBlk + wn*64 + ni*8 + 2*t4;
            float v0 = acc[mi][ni][0], v1 = acc[mi][ni][1];
            float v2 = acc[mi][ni][2], v3 = acc[mi][ni][3];
            if (EPI == 0 || EPI == 2) {
                *(__half2*)&((__half*)Cb)[(long)r0*ldc + c0]     = __floats2half2_rn(v0, v1);
                *(__half2*)&((__half*)Cb)[(long)(r0+8)*ldc + c0] = __floats2half2_rn(v2, v3);
            } else {
                *(float2*)&((float*)Cb)[(long)r0*ldc + c0]     = make_float2(v0, v1);
                *(float2*)&((float*)Cb)[(long)(r0+8)*ldc + c0] = make_float2(v2, v3);
            }
        }
    }
}

// ================= 256x256 fp16 GEMM, 512 threads, 3-stage =================
#define A3SZ (256*144)        // 36864 B
#define STG3 (2*A3SZ)         // 73728 B (A+B)
#define SMEM3 (3*STG3)        // 221184

template<int EPI, typename OutT>
__global__ void __launch_bounds__(512, 1)
hgemm512(const __half* __restrict__ A, const __half* __restrict__ Bm, OutT* __restrict__ C,
         int K, int lda, int ldb, int ldc,
         const float* __restrict__ bias, const float* __restrict__ resid)
{
    extern __shared__ char smem[];
    const uint32_t sbase = smem_u32(smem);

    int tid = threadIdx.x;
    int warp = tid >> 5, lane = tid & 31;
    int wm = warp >> 2, wn = warp & 3;     // 4x4 warps, 64x64 warp tile
    int rowBlk = blockIdx.y * 256;
    int colBlk = blockIdx.x * 256;

    float acc[4][8][4];
    #pragma unroll
    for (int mi = 0; mi < 4; mi++)
        #pragma unroll
        for (int ni = 0; ni < 8; ni++)
            #pragma unroll
            for (int r = 0; r < 4; r++) acc[mi][ni][r] = 0.0f;

    uint32_t aoff = (uint32_t)(((wm*64 + (lane & 15)) * 72 + ((lane >> 4) << 3)) * 2);
    uint32_t boff = (uint32_t)(((wn*64 + (lane & 7) + ((lane >> 4) << 3)) * 72 + (lane & 8)) * 2);

    auto load_chunk = [&](int ck, int s) {
        uint32_t ab = sbase + s*STG3;
        uint32_t bb = ab + A3SZ;
        const __half* Ag = A + (long)rowBlk * lda + ck*64;
        const __half* Bg = Bm + (long)colBlk * ldb + ck*64;
        #pragma unroll
        for (int it = 0; it < 4; it++) {
            int idx = tid + it*512;
            int row = idx >> 3, gq = idx & 7;
            cpa16(ab + row*144 + gq*16, Ag + (long)row*lda + gq*8);
        }
        #pragma unroll
        for (int it = 0; it < 4; it++) {
            int idx = tid + it*512;
            int row = idx >> 3, gq = idx & 7;
            cpa16(bb + row*144 + gq*16, Bg + (long)row*ldb + gq*8);
        }
        cp_commit();
    };

    int nc = K >> 6;
    load_chunk(0, 0);
    load_chunk(1, 1);

    for (int c = 0; c < nc; c++) {
        if (c + 1 < nc) cp_wait<1>(); else cp_wait<0>();
        __syncthreads();
        if (c + 2 < nc) load_chunk(c + 2, (c + 2) % 3);

        uint32_t As = sbase + (c % 3)*STG3;
        uint32_t Bs = As + A3SZ;
        #pragma unroll
        for (int kk = 0; kk < 64; kk += 16) {
            uint32_t a[4][4], b[4][4];
            #pragma unroll
            for (int mi = 0; mi < 4; mi++)
                ldsm_x4(a[mi], As + aoff + mi*2304u + kk*2);
            #pragma unroll
            for (int j = 0; j < 4; j++)
                ldsm_x4(b[j], Bs + boff + j*2304u + kk*2);
            #pragma unroll
            for (int mi = 0; mi < 4; mi++)
                #pragma unroll
                for (int ni = 0; ni < 8; ni++)
                    mma_f16(acc[mi][ni], a[mi][0], a[mi][1], a[mi][2], a[mi][3],
                            b[ni >> 1][(ni & 1)*2], b[ni >> 1][(ni & 1)*2 + 1]);
        }
        __syncthreads();
    }

    int g = lane >> 2, t4 = lane & 3;
    #pragma unroll
    for (int mi = 0; mi < 4; mi++) {
        #pragma unroll
        for (int ni = 0; ni < 8; ni++) {
            int r0 = rowBlk + wm*64 + mi*16 + g;
            int c0 = colBlk + wn*64 + ni*8 + 2*t4;
            float v0 = acc[mi][ni][0], v1 = acc[mi][ni][1];
            float v2 = acc[mi][ni][2], v3 = acc[mi][ni][3];
            if (EPI >= 2) {
                float b0 = bias[c0], b1 = bias[c0+1];
                v0 += b0; v1 += b1; v2 += b0; v3 += b1;
            }
            if (EPI == 2) {
                v0 = gelu_exact(v0); v1 = gelu_exact(v1);
                v2 = gelu_exact(v2); v3 = gelu_exact(v3);
            }
            if (EPI == 3) {
                const float2 ra = *(const float2*)&resid[(long)r0*ldc + c0];
                const float2 rb = *(const float2*)&resid[(long)(r0+8)*ldc + c0];
                v0 += ra.x; v1 += ra.y; v2 += rb.x; v3 += rb.y;
            }
            if (EPI == 2) {
                *(__half2*)&((__half*)C)[(long)r0*ldc + c0]     = __floats2half2_rn(v0, v1);
                *(__half2*)&((__half*)C)[(long)(r0+8)*ldc + c0] = __floats2half2_rn(v2, v3);
            } else {
                *(float2*)&((float*)C)[(long)r0*ldc + c0]     = make_float2(v0, v1);
                *(float2*)&((float*)C)[(long)(r0+8)*ldc + c0] = make_float2(v2, v3);
            }
        }
    }
}

// ---------------- transpose fp32 -> fp16 ----------------
__global__ void transpose_h(const float* __restrict__ src, __half* __restrict__ dst,
                            int R, int Ccol)
{
    __shared__ float t[32][33];
    int c0 = blockIdx.x * 32, r0 = blockIdx.y * 32;
    int x = c0 + threadIdx.x;
    #pragma unroll
    for (int j = threadIdx.y; j < 32; j += 8)
        t[j][threadIdx.x] = src[(long)(r0 + j) * Ccol + x];
    __syncthreads();
    int x2 = r0 + threadIdx.x;
    #pragma unroll
    for (int j = threadIdx.y; j < 32; j += 8)
        dst[(long)(c0 + j) * R + x2] = __float2half_rn(t[threadIdx.x][j]);
}

// ---------------- fused conv QKV, 4-position register blocking ----------------
__global__ void __launch_bounds__(256, 2) conv_qkv(const float* __restrict__ x,
                                                   const float* __restrict__ qw,
                                                   const float* __restrict__ kw,
                                                   const float* __restrict__ vw)
{
    __shared__ float sp[3][P_+2][P_+2];
    __shared__ float swq[81], swk[81], swv[81];
    int tid = threadIdx.x;
    int patch = blockIdx.x;
    int b = patch >> 8;
    int n = patch & 255;
    const float* xp = x + (long)patch * C_;

    if (tid < 81) { swq[tid] = qw[tid]; swk[tid] = kw[tid]; swv[tid] = vw[tid]; }
    for (int i = tid; i < 3*(P_+2)*(P_+2); i += 256)
        ((float*)sp)[i] = 0.0f;
    __syncthreads();
    for (int i = tid; i < C_; i += 256) {
        int ch = i >> 10;
        int s  = i & 1023;
        sp[ch][(s >> 5)+1][(s & 31)+1] = xp[i];
    }
    __syncthreads();

    int pos0 = tid * 4;
    int yy = pos0 >> 5, xx = pos0 & 31;
    float aq[3][4], ak[3][4], av[3][4];
    #pragma unroll
    for (int o = 0; o < 3; o++)
        #pragma unroll
        for (int p = 0; p < 4; p++) { aq[o][p] = 0.f; ak[o][p] = 0.f; av[o][p] = 0.f; }

    #pragma unroll
    for (int i = 0; i < 3; i++) {
        #pragma unroll
        for (int dy = 0; dy < 3; dy++) {
            float r[6];
            #pragma unroll
            for (int t = 0; t < 6; t++) r[t] = sp[i][yy+dy][xx+t];
            #pragma unroll
            for (int dx = 0; dx < 3; dx++) {
                int wi = i*9 + dy*3 + dx;
                float wq0 = swq[wi], wq1 = swq[27+wi], wq2 = swq[54+wi];
                float wk0 = swk[wi], wk1 = swk[27+wi], wk2 = swk[54+wi];
                float wv0 = swv[wi], wv1 = swv[27+wi], wv2 = swv[54+wi];
                #pragma unroll
                for (int p = 0; p < 4; p++) {
                    float val = r[dx + p];
                    aq[0][p] = fmaf(val, wq0, aq[0][p]);
                    aq[1][p] = fmaf(val, wq1, aq[1][p]);
                    aq[2][p] = fmaf(val, wq2, aq[2][p]);
                    ak[0][p] = fmaf(val, wk0, ak[0][p]);
                    ak[1][p] = fmaf(val, wk1, ak[1][p]);
                    ak[2][p] = fmaf(val, wk2, ak[2][p]);
                    av[0][p] = fmaf(val, wv0, av[0][p]);
                    av[1][p] = fmaf(val, wv1, av[1][p]);
                    av[2][p] = fmaf(val, wv2, av[2][p]);
                }
            }
        }
    }

    #pragma unroll
    for (int o = 0; o < 3; o++) {
        int c0 = o*1024 + pos0;
        int h = c0 / HD_;
        int d = c0 - h*HD_;
        long bh = (long)(b*H_ + h);
        long base = (bh*N_ + n)*HD_ + d;
        *(__half2*)&g_hq[base]   = __floats2half2_rn(aq[o][0], aq[o][1]);
        *(__half2*)&g_hq[base+2] = __floats2half2_rn(aq[o][2], aq[o][3]);
        *(__half2*)&g_hk[base]   = __floats2half2_rn(ak[o][0], ak[o][1]);
        *(__half2*)&g_hk[base+2] = __floats2half2_rn(ak[o][2], ak[o][3]);
        #pragma unroll
        for (int p = 0; p < 4; p++)
            g_hvt[(bh*HD_ + d + p)*N_ + n] = __float2half_rn(av[o][p]);
    }
}

// ---------------- fused softmax + re-attention + BN -> fp16 ----------------
__global__ void __launch_bounds__(256) softmax_reatten(
    const float* __restrict__ attn, __half* __restrict__ attn2,
    const float* __restrict__ w,  const float* __restrict__ rb,
    const float* __restrict__ g,  const float* __restrict__ bta,
    const float* __restrict__ mean, const float* __restrict__ var)
{
    __shared__ float sp[8][256];
    __shared__ float sw[64], sscale[8], sshift[8];
    int tid = threadIdx.x;
    int h = tid >> 5, lane = tid & 31;
    if (tid < 64) sw[tid] = w[tid];
    if (tid < 8) {
        float inv = rsqrtf(var[tid] + 1e-5f);
        float gi = g[tid] * inv;
        sscale[tid] = gi;
        sshift[tid] = bta[tid] + (rb[tid] - mean[tid]) * gi;
    }
    int b = blockIdx.x >> 8, n = blockIdx.x & 255;
    const float scale = 0.051031036307982884f;
    const float* row = attn + (((long)(b*H_ + h))*N_ + n)*N_;

    float v[8];
    #pragma unroll
    for (int j = 0; j < 8; j++) v[j] = row[lane + j*32] * scale;
    float m = v[0];
    #pragma unroll
    for (int j = 1; j < 8; j++) m = fmaxf(m, v[j]);
    #pragma unroll
    for (int o = 16; o > 0; o >>= 1) m = fmaxf(m, __shfl_xor_sync(0xffffffffu, m, o));
    float s = 0.0f;
    float e[8];
    #pragma unroll
    for (int j = 0; j < 8; j++) { e[j] = __expf(v[j] - m); s += e[j]; }
    #pragma unroll
    for (int o = 16; o > 0; o >>= 1) s += __shfl_xor_sync(0xffffffffu, s, o);
    float inv = 1.0f / s;
    #pragma unroll
    for (int j = 0; j < 8; j++) sp[h][lane + j*32] = e[j] * inv;
    __syncthreads();

    float in[8];
    #pragma unroll
    for (int i = 0; i < 8; i++) in[i] = sp[i][tid];
    #pragma unroll
    for (int o = 0; o < 8; o++) {
        float acc = 0.0f;
        #pragma unroll
        for (int i = 0; i < 8; i++) acc = fmaf(sw[o*8 + i], in[i], acc);
        attn2[(((long)(b*H_ + o))*N_ + n)*N_ + tid] =
            __float2half_rn(acc * sscale[o] + sshift[o]);
    }
}

// ---------------- LayerNorm: two-level stats ----------------
__global__ void ln_part(const float* __restrict__ y)
{
    __shared__ double rs[8], rq[8];
    int b = blockIdx.y, seg = blockIdx.x;
    const float* p = y + (long)b * NC_ + (long)seg * (NC_/32);
    double s = 0.0, q = 0.0;
    for (int i = threadIdx.x; i < NC_/32; i += 256) {
        double v = (double)p[i];
        s += v; q += v * v;
    }
    #pragma unroll
    for (int o = 16; o > 0; o >>= 1) {
        s += __shfl_xor_sync(0xffffffffu, s, o);
        q += __shfl_xor_sync(0xffffffffu, q, o);
    }
    int lane = threadIdx.x & 31, wid = threadIdx.x >> 5;
    if (lane == 0) { rs[wid] = s; rq[wid] = q; }
    __syncthreads();
    if (threadIdx.x == 0) {
        double S = 0.0, Q = 0.0;
        #pragma unroll
        for (int i = 0; i < 8; i++) { S += rs[i]; Q += rq[i]; }
        g_part[(b*32 + seg)*2]     = S;
        g_part[(b*32 + seg)*2 + 1] = Q;
    }
}

__global__ void ln_fin(float* __restrict__ stats)
{
    int b = blockIdx.x, t = threadIdx.x;
    double s = g_part[(b*32 + t)*2];
    double q = g_part[(b*32 + t)*2 + 1];
    #pragma unroll
    for (int o = 16; o > 0; o >>= 1) {
        s += __shfl_xor_sync(0xffffffffu, s, o);
        q += __shfl_xor_sync(0xffffffffu, q, o);
    }
    if (t == 0) {
        double mu  = s / (double)NC_;
        double var = q / (double)NC_ - mu * mu;
        stats[b*2]   = (float)mu;
        stats[b*2+1] = (float)rsqrt(var + 1e-5);
    }
}

__global__ void ln_apply_dual(const float* __restrict__ y, const float* __restrict__ stats,
                              const float* __restrict__ g, const float* __restrict__ beta,
                              float* __restrict__ outf, __half* __restrict__ outh)
{
    long i = (long)blockIdx.x * blockDim.x + threadIdx.x;
    int b = (int)(i / NC_);
    int r = (int)(i % NC_);
    float v = (y[i] - stats[b*2]) * stats[b*2+1] * g[r] + beta[r];
    outf[i] = v;
    outh[i] = __float2half_rn(v);
}

__global__ void ln_apply(const float* __restrict__ y, const float* __restrict__ stats,
                         const float* __restrict__ g, const float* __restrict__ beta,
                         float* __restrict__ out)
{
    long i = (long)blockIdx.x * blockDim.x + threadIdx.x;
    int b = (int)(i / NC_);
    int r = (int)(i % NC_);
    out[i] = (y[i] - stats[b*2]) * stats[b*2+1] * g[r] + beta[r];
}

// ---------------- launch ----------------
extern "C" void kernel_launch(void* const* d_in, const int* in_sizes, int n_in,
                              void* d_out, int out_size)
{
    const float* x        = (const float*)d_in[0];
    const float* qconv_w  = (const float*)d_in[1];
    const float* kconv_w  = (const float*)d_in[2];
    const float* vconv_w  = (const float*)d_in[3];
    const float* reat_w   = (const float*)d_in[4];
    const float* reat_b   = (const float*)d_in[5];
    const float* bn_gamma = (const float*)d_in[6];
    const float* bn_beta  = (const float*)d_in[7];
    const float* bn_mean  = (const float*)d_in[8];
    const float* bn_var   = (const float*)d_in[9];
    const float* proj_w   = (const float*)d_in[10];
    const float* proj_b   = (const float*)d_in[11];
    const float* ln_g     = (const float*)d_in[12];
    const float* ln_b     = (const float*)d_in[13];
    const float* ff_w1    = (const float*)d_in[14];
    const float* ff_b1    = (const float*)d_in[15];
    const float* ff_w2    = (const float*)d_in[16];
    const float* ff_b2    = (const float*)d_in[17];
    float* out = (float*)d_out;

    __half *pq, *pk, *pvt, *pattn2, *pctx, *pynh, *ph, *pprojT, *pw1T, *pw2T;
    float *pattn, *py1, *pyn, *py2, *pstats;
    cudaGetSymbolAddress((void**)&pq,     g_hq);
    cudaGetSymbolAddress((void**)&pk,     g_hk);
    cudaGetSymbolAddress((void**)&pvt,    g_hvt);
    cudaGetSymbolAddress((void**)&pattn2, g_hattn2);
    cudaGetSymbolAddress((void**)&pctx,   g_hctx);
    cudaGetSymbolAddress((void**)&pynh,   g_hynh);
    cudaGetSymbolAddress((void**)&ph,     g_hh);
    cudaGetSymbolAddress((void**)&pprojT, g_hprojT);
    cudaGetSymbolAddress((void**)&pw1T,   g_hw1T);
    cudaGetSymbolAddress((void**)&pw2T,   g_hw2T);
    cudaGetSymbolAddress((void**)&pattn,  g_attn);
    cudaGetSymbolAddress((void**)&py1,    g_y1);
    cudaGetSymbolAddress((void**)&pyn,    g_yn);
    cudaGetSymbolAddress((void**)&py2,    g_y2);
    cudaGetSymbolAddress((void**)&pstats, g_stats);

    cudaFuncSetAttribute(hgemm<0,__half>,    cudaFuncAttributeMaxDynamicSharedMemorySize, HSMEM);
    cudaFuncSetAttribute(hgemm256<1,float>,  cudaFuncAttributeMaxDynamicSharedMemorySize, SMEM2);
    cudaFuncSetAttribute(hgemm512<2,__half>, cudaFuncAttributeMaxDynamicSharedMemorySize, SMEM3);
    cudaFuncSetAttribute(hgemm512<3,float>,  cudaFuncAttributeMaxDynamicSharedMemorySize, SMEM3);

    // 1. fused conv QKV  (launch 0)
    conv_qkv<<<B_*N_, 256>>>(x, qconv_w, kconv_w, vconv_w);

    // 2. S = Q K^T  (launch 1)
    hgemm256<1,float><<<dim3(1,2,BH_), 512, SMEM2>>>(pq, pk, pattn,
        HD_, HD_, HD_, N_, (long)N_*HD_, (long)N_*HD_, 1, 65536L, 0L, nullptr, nullptr);

    // 3. fused softmax + re-attention (launch 2)
    softmax_reatten<<<B_*N_, 256>>>(pattn, pattn2, reat_w, reat_b,
                                    bn_gamma, bn_beta, bn_mean, bn_var);

    // 4. ctx = attn2 @ V (launch 3)
    hgemm<0,__half><<<dim3(3,2,BH_), 256, HSMEM>>>(pattn2, pvt, pctx,
        N_, N_, N_, C_, 65536L, (long)HD_*N_, H_, (long)N_*C_, (long)HD_, nullptr, nullptr);

    // 5. proj weight transpose (launch 4)
    {
        dim3 blk(32, 8);
        transpose_h<<<dim3(C_/32, C_/32), blk>>>(proj_w, pprojT, C_, C_);
    }

    // 6. y1 = x + ctx @ proj_w + proj_b  (launch 5 — ncu target)
    // K=C, lda=C (ctx rows), ldb=C (projT rows are K-contig, stride C), ldc=C
    hgemm512<3,float><<<dim3(C_/256, (B_*N_)/256), 512, SMEM3>>>(pctx, pprojT, py1,
        C_, C_, C_, C_, proj_b, x);

    // 7. FFN weight transposes
    {
        dim3 blk(32, 8);
        transpose_h<<<dim3(FF_/32, C_/32), blk>>>(ff_w1, pw1T, C_, FF_);
        transpose_h<<<dim3(C_/32, FF_/32), blk>>>(ff_w2, pw2T, FF_, C_);
    }

    // 8. LN1
    ln_part<<<dim3(32, B_), 256>>>(py1);
    ln_fin<<<B_, 32>>>(pstats);
    ln_apply_dual<<<QKV_SZ/256, 256>>>(py1, pstats, ln_g, ln_b, pyn, pynh);

    // 9. h = gelu(yn @ ff_w1 + b1)
    // K=C, lda=C (yn), ldb=C (w1T rows stride C), ldc=FF
    hgemm512<2,__half><<<dim3(FF_/256, (B_*N_)/256), 512, SMEM3>>>(pynh, pw1T, ph,
        C_, C_, C_, FF_, ff_b1, nullptr);

    // 10. y2 = yn + h @ ff_w2 + b2
    // K=FF, lda=FF (h), ldb=FF (w2T rows stride FF), ldc=C
    hgemm512<3,float><<<dim3(C_/256, (B_*N_)/256), 512, SMEM3>>>(ph, pw2T, py2,
        FF_, FF_, FF_, C_, ff_b2, pyn);

    // 11. LN2 -> out
    ln_part<<<dim3(32, B_), 256>>>(py2);
    ln_fin<<<B_, 32>>>(pstats);
    ln_apply<<<QKV_SZ/256, 256>>>(py2, pstats, ln_g, ln_b, out);
}

// round 10
// speedup vs baseline: 2.8348x; 2.8348x over previous
#include <cuda_runtime.h>
#include <cuda_fp16.h>
#include <math.h>
#include <stdint.h>

// ---------------- problem constants ----------------
#define B_   8
#define N_   256
#define C_   3072
#define H_   8
#define HD_  384
#define FF_  12288
#define P_   32
#define NC_  (N_*C_)
#define BH_  (B_*H_)
#define QKV_SZ   (B_*N_*C_)
#define ATT_SZ   (B_*H_*N_*N_)
#define HBUF_SZ  (B_*N_*FF_)

// ---------------- device scratch ----------------
__device__ __align__(256) __half g_hq[QKV_SZ];
__device__ __align__(256) __half g_hk[QKV_SZ];
__device__ __align__(256) __half g_hvt[QKV_SZ];     // V^T: (BH, hd, N)
__device__ __align__(256) __half g_hattn2[ATT_SZ];
__device__ __align__(256) __half g_hctx[QKV_SZ];
__device__ __align__(256) __half g_hynh[QKV_SZ];
__device__ __align__(256) __half g_hh[HBUF_SZ];
__device__ __align__(256) __half g_hprojT[C_*C_];
__device__ __align__(256) __half g_hw1T[(long)C_*FF_];
__device__ __align__(256) __half g_hw2T[(long)C_*FF_];
__device__ float g_attn[ATT_SZ];
__device__ float g_y1[QKV_SZ];
__device__ float g_yn[QKV_SZ];
__device__ float g_y2[QKV_SZ];
__device__ float g_stats[B_*2];
__device__ double g_part[B_*32*2];

// ---------------- helpers ----------------
__device__ __forceinline__ float gelu_exact(float x) {
    return 0.5f * x * (1.0f + erff(x * 0.70710678118654752f));
}
__device__ __forceinline__ uint32_t smem_u32(const void* p) {
    return (uint32_t)__cvta_generic_to_shared(p);
}
__device__ __forceinline__ void cpa16(uint32_t dst, const void* src) {
    asm volatile("cp.async.cg.shared.global [%0], [%1], 16;\n" :: "r"(dst), "l"(src));
}
__device__ __forceinline__ void cp_commit() { asm volatile("cp.async.commit_group;\n"); }
template<int NN> __device__ __forceinline__ void cp_wait() {
    asm volatile("cp.async.wait_group %0;\n" :: "n"(NN));
}
__device__ __forceinline__ void ldsm_x4(uint32_t* r, uint32_t addr) {
    asm volatile("ldmatrix.sync.aligned.m8n8.x4.shared.b16 {%0,%1,%2,%3}, [%4];"
                 : "=r"(r[0]), "=r"(r[1]), "=r"(r[2]), "=r"(r[3]) : "r"(addr));
}
__device__ __forceinline__ void mma_f16(float c[4], uint32_t a0, uint32_t a1, uint32_t a2,
                                        uint32_t a3, uint32_t b0, uint32_t b1) {
    asm volatile(
        "mma.sync.aligned.m16n8k16.row.col.f32.f16.f16.f32 "
        "{%0,%1,%2,%3},{%4,%5,%6,%7},{%8,%9},{%0,%1,%2,%3};\n"
        : "+f"(c[0]), "+f"(c[1]), "+f"(c[2]), "+f"(c[3])
        : "r"(a0), "r"(a1), "r"(a2), "r"(a3), "r"(b0), "r"(b1));
}

// ================= 128x128 fp16 GEMM (attention AV) =================
#define ASZ  (128*72*2)
#define STG  (2*ASZ)
#define HSMEM (2*STG)

template<int EPI, typename OutT>
__global__ void __launch_bounds__(256, 2)
hgemm(const __half* __restrict__ A, const __half* __restrict__ Bm, OutT* __restrict__ C,
      int K, int lda, int ldb, int ldc,
      long sA, long sB, int zdiv, long sC1, long sC2,
      const float* __restrict__ bias, const float* __restrict__ resid)
{
    extern __shared__ char smem[];
    const uint32_t sbase = smem_u32(smem);

    int tid = threadIdx.x;
    int warp = tid >> 5, lane = tid & 31;
    int wm = warp >> 2, wn = warp & 3;
    int z = blockIdx.z;
    const __half* Ab = A + (long)z * sA;
    const __half* Bb = Bm + (long)z * sB;
    long coff = (long)(z / zdiv) * sC1 + (long)(z % zdiv) * sC2;
    OutT* Cb = C + coff;
    int rowBlk = blockIdx.y * 128;
    int colBlk = blockIdx.x * 128;

    float acc[4][4][4];
    #pragma unroll
    for (int mi = 0; mi < 4; mi++)
        #pragma unroll
        for (int ni = 0; ni < 4; ni++)
            #pragma unroll
            for (int r = 0; r < 4; r++) acc[mi][ni][r] = 0.0f;

    uint32_t aoff = (uint32_t)(((wm*64 + (lane & 15)) * 72 + ((lane >> 4) << 3)) * 2);
    uint32_t boff0 = (uint32_t)(((wn*32 + (lane & 7) + ((lane >> 4) << 3)) * 72 + (lane & 8)) * 2);
    uint32_t boff1 = boff0 + 16u*144u;

    auto load_chunk = [&](int ck, int s) {
        uint32_t ab = sbase + s*STG;
        uint32_t bb = ab + ASZ;
        const __half* Ag = Ab + (long)rowBlk * lda + ck*64;
        const __half* Bg = Bb + (long)colBlk * ldb + ck*64;
        #pragma unroll
        for (int it = 0; it < 4; it++) {
            int idx = tid + it*256;
            int row = idx >> 3, gq = idx & 7;
            cpa16(ab + row*144 + gq*16, Ag + (long)row*lda + gq*8);
        }
        #pragma unroll
        for (int it = 0; it < 4; it++) {
            int idx = tid + it*256;
            int row = idx >> 3, gq = idx & 7;
            cpa16(bb + row*144 + gq*16, Bg + (long)row*ldb + gq*8);
        }
        cp_commit();
    };

    int nc = K >> 6;
    load_chunk(0, 0);

    for (int c = 0; c < nc; c++) {
        int s = c & 1;
        if (c + 1 < nc) { load_chunk(c + 1, s ^ 1); cp_wait<1>(); }
        else            { cp_wait<0>(); }
        __syncthreads();

        uint32_t As = sbase + s*STG;
        uint32_t Bs = As + ASZ;
        #pragma unroll
        for (int kk = 0; kk < 64; kk += 16) {
            uint32_t a[4][4], b[2][4];
            #pragma unroll
            for (int mi = 0; mi < 4; mi++)
                ldsm_x4(a[mi], As + aoff + mi*2304u + kk*2);
            ldsm_x4(b[0], Bs + boff0 + kk*2);
            ldsm_x4(b[1], Bs + boff1 + kk*2);
            #pragma unroll
            for (int mi = 0; mi < 4; mi++)
                #pragma unroll
                for (int ni = 0; ni < 4; ni++)
                    mma_f16(acc[mi][ni], a[mi][0], a[mi][1], a[mi][2], a[mi][3],
                            b[ni >> 1][(ni & 1)*2], b[ni >> 1][(ni & 1)*2 + 1]);
        }
        __syncthreads();
    }

    int g = lane >> 2, t4 = lane & 3;
    #pragma unroll
    for (int mi = 0; mi < 4; mi++) {
        #pragma unroll
        for (int ni = 0; ni < 4; ni++) {
            int r0 = rowBlk + wm*64 + mi*16 + g;
            int c0 = colBlk + wn*32 + ni*8 + 2*t4;
            float v0 = acc[mi][ni][0], v1 = acc[mi][ni][1];
            float v2 = acc[mi][ni][2], v3 = acc[mi][ni][3];
            if (EPI == 0 || EPI == 2) {
                *(__half2*)&((__half*)Cb)[(long)r0*ldc + c0]     = __floats2half2_rn(v0, v1);
                *(__half2*)&((__half*)Cb)[(long)(r0+8)*ldc + c0] = __floats2half2_rn(v2, v3);
            } else {
                *(float2*)&((float*)Cb)[(long)r0*ldc + c0]     = make_float2(v0, v1);
                *(float2*)&((float*)Cb)[(long)(r0+8)*ldc + c0] = make_float2(v2, v3);
            }
        }
    }
}

// ================= 128x256 fp16 GEMM, 512 threads, 4-stage (QK) =================
#define A2SZ (128*144)
#define B2SZ (256*144)
#define STG2 (A2SZ + B2SZ)    // 55296
#define SMEM2 (4*STG2)        // 221184

template<int EPI, typename OutT>
__global__ void __launch_bounds__(512, 1)
hgemm256(const __half* __restrict__ A, const __half* __restrict__ Bm, OutT* __restrict__ C,
         int K, int lda, int ldb, int ldc,
         long sA, long sB, int zdiv, long sC1, long sC2,
         const float* __restrict__ bias, const float* __restrict__ resid)
{
    extern __shared__ char smem[];
    const uint32_t sbase = smem_u32(smem);

    int tid = threadIdx.x;
    int warp = tid >> 5, lane = tid & 31;
    int wm = warp >> 2, wn = warp & 3;     // 4x4 warp grid, 32x64 warp tile
    int z = blockIdx.z;
    const __half* Ab = A + (long)z * sA;
    const __half* Bb = Bm + (long)z * sB;
    long coff = (long)(z / zdiv) * sC1 + (long)(z % zdiv) * sC2;
    OutT* Cb = C + coff;
    int rowBlk = blockIdx.y * 128;
    int colBlk = blockIdx.x * 256;

    float acc[2][8][4];
    #pragma unroll
    for (int mi = 0; mi < 2; mi++)
        #pragma unroll
        for (int ni = 0; ni < 8; ni++)
            #pragma unroll
            for (int r = 0; r < 4; r++) acc[mi][ni][r] = 0.0f;

    uint32_t aoff = (uint32_t)(((wm*32 + (lane & 15)) * 72 + ((lane >> 4) << 3)) * 2);
    uint32_t boff = (uint32_t)(((wn*64 + (lane & 7) + ((lane >> 4) << 3)) * 72 + (lane & 8)) * 2);

    auto load_chunk = [&](int ck, int s) {
        uint32_t ab = sbase + s*STG2;
        uint32_t bb = ab + A2SZ;
        const __half* Ag = Ab + (long)rowBlk * lda + ck*64;
        const __half* Bg = Bb + (long)colBlk * ldb + ck*64;
        #pragma unroll
        for (int it = 0; it < 2; it++) {
            int idx = tid + it*512;
            int row = idx >> 3, gq = idx & 7;
            cpa16(ab + row*144 + gq*16, Ag + (long)row*lda + gq*8);
        }
        #pragma unroll
        for (int it = 0; it < 4; it++) {
            int idx = tid + it*512;
            int row = idx >> 3, gq = idx & 7;
            cpa16(bb + row*144 + gq*16, Bg + (long)row*ldb + gq*8);
        }
        cp_commit();
    };

    int nc = K >> 6;
    load_chunk(0, 0);
    if (nc > 1) load_chunk(1, 1); else cp_commit();
    if (nc > 2) load_chunk(2, 2); else cp_commit();

    for (int c = 0; c < nc; c++) {
        cp_wait<2>();
        __syncthreads();
        if (c + 3 < nc) load_chunk(c + 3, (c + 3) & 3);
        else            cp_commit();

        uint32_t As = sbase + (c & 3)*STG2;
        uint32_t Bs = As + A2SZ;

        uint32_t af[2][2][4], bf[2][4][4];
        #pragma unroll
        for (int mi = 0; mi < 2; mi++) ldsm_x4(af[0][mi], As + aoff + mi*2304u);
        #pragma unroll
        for (int j = 0; j < 4; j++)    ldsm_x4(bf[0][j],  Bs + boff + j*2304u);

        #pragma unroll
        for (int ki = 0; ki < 4; ki++) {
            int cur = ki & 1;
            if (ki < 3) {
                int kk2 = (ki + 1) * 16 * 2;
                #pragma unroll
                for (int mi = 0; mi < 2; mi++) ldsm_x4(af[cur^1][mi], As + aoff + mi*2304u + kk2);
                #pragma unroll
                for (int j = 0; j < 4; j++)    ldsm_x4(bf[cur^1][j],  Bs + boff + j*2304u + kk2);
            }
            #pragma unroll
            for (int mi = 0; mi < 2; mi++)
                #pragma unroll
                for (int ni = 0; ni < 8; ni++)
                    mma_f16(acc[mi][ni], af[cur][mi][0], af[cur][mi][1],
                            af[cur][mi][2], af[cur][mi][3],
                            bf[cur][ni >> 1][(ni & 1)*2], bf[cur][ni >> 1][(ni & 1)*2 + 1]);
        }
    }

    __syncthreads();
    int g = lane >> 2, t4 = lane & 3;
    #pragma unroll
    for (int mi = 0; mi < 2; mi++) {
        #pragma unroll
        for (int ni = 0; ni < 8; ni++) {
            int r0 = rowBlk + wm*32 + mi*16 + g;
            int c0 = colBlk + wn*64 + ni*8 + 2*t4;
            float v0 = acc[mi][ni][0], v1 = acc[mi][ni][1];
            float v2 = acc[mi][ni][2], v3 = acc[mi][ni][3];
            if (EPI == 0 || EPI == 2) {
                *(__half2*)&((__half*)Cb)[(long)r0*ldc + c0]     = __floats2half2_rn(v0, v1);
                *(__half2*)&((__half*)Cb)[(long)(r0+8)*ldc + c0] = __floats2half2_rn(v2, v3);
            } else {
                *(float2*)&((float*)Cb)[(long)r0*ldc + c0]     = make_float2(v0, v1);
                *(float2*)&((float*)Cb)[(long)(r0+8)*ldc + c0] = make_float2(v2, v3);
            }
        }
    }
}

// ================= 128x192 fp16 GEMM, 384 threads, 4-stage (big GEMMs) =================
#define A4SZ (128*144)        // 18432
#define B4SZ (192*144)        // 27648
#define STG4 (A4SZ + B4SZ)    // 46080
#define SMEM4 (4*STG4)        // 184320

template<int EPI, typename OutT>
__global__ void __launch_bounds__(384, 1)
hgemm192(const __half* __restrict__ A, const __half* __restrict__ Bm, OutT* __restrict__ C,
         int K, int lda, int ldb, int ldc,
         const float* __restrict__ bias, const float* __restrict__ resid)
{
    extern __shared__ char smem[];
    const uint32_t sbase = smem_u32(smem);

    int tid = threadIdx.x;
    int warp = tid >> 5, lane = tid & 31;
    int wm = warp / 3, wn = warp % 3;      // 4x3 warp grid, 32x64 warp tile
    int rowBlk = blockIdx.y * 128;
    int colBlk = blockIdx.x * 192;

    float acc[2][8][4];
    #pragma unroll
    for (int mi = 0; mi < 2; mi++)
        #pragma unroll
        for (int ni = 0; ni < 8; ni++)
            #pragma unroll
            for (int r = 0; r < 4; r++) acc[mi][ni][r] = 0.0f;

    uint32_t aoff = (uint32_t)(((wm*32 + (lane & 15)) * 72 + ((lane >> 4) << 3)) * 2);
    uint32_t boff = (uint32_t)(((wn*64 + (lane & 7) + ((lane >> 4) << 3)) * 72 + (lane & 8)) * 2);

    auto load_chunk = [&](int ck, int s) {
        uint32_t ab = sbase + s*STG4;
        uint32_t bb = ab + A4SZ;
        const __half* Ag = A + (long)rowBlk * lda + ck*64;
        const __half* Bg = Bm + (long)colBlk * ldb + ck*64;
        #pragma unroll
        for (int it = 0; it < 3; it++) {           // A: 1024 granules over 384 thr
            int idx = tid + it*384;
            if (idx < 1024) {
                int row = idx >> 3, gq = idx & 7;
                cpa16(ab + row*144 + gq*16, Ag + (long)row*lda + gq*8);
            }
        }
        #pragma unroll
        for (int it = 0; it < 4; it++) {           // B: 1536 granules = 4*384 exactly
            int idx = tid + it*384;
            int row = idx >> 3, gq = idx & 7;
            cpa16(bb + row*144 + gq*16, Bg + (long)row*ldb + gq*8);
        }
        cp_commit();
    };

    int nc = K >> 6;
    load_chunk(0, 0);
    if (nc > 1) load_chunk(1, 1); else cp_commit();
    if (nc > 2) load_chunk(2, 2); else cp_commit();

    for (int c = 0; c < nc; c++) {
        cp_wait<2>();
        __syncthreads();
        if (c + 3 < nc) load_chunk(c + 3, (c + 3) & 3);
        else            cp_commit();

        uint32_t As = sbase + (c & 3)*STG4;
        uint32_t Bs = As + A4SZ;

        uint32_t af[2][2][4], bf[2][4][4];
        #pragma unroll
        for (int mi = 0; mi < 2; mi++) ldsm_x4(af[0][mi], As + aoff + mi*2304u);
        #pragma unroll
        for (int j = 0; j < 4; j++)    ldsm_x4(bf[0][j],  Bs + boff + j*2304u);

        #pragma unroll
        for (int ki = 0; ki < 4; ki++) {
            int cur = ki & 1;
            if (ki < 3) {
                int kk2 = (ki + 1) * 32;
                #pragma unroll
                for (int mi = 0; mi < 2; mi++) ldsm_x4(af[cur^1][mi], As + aoff + mi*2304u + kk2);
                #pragma unroll
                for (int j = 0; j < 4; j++)    ldsm_x4(bf[cur^1][j],  Bs + boff + j*2304u + kk2);
            }
            #pragma unroll
            for (int mi = 0; mi < 2; mi++)
                #pragma unroll
                for (int ni = 0; ni < 8; ni++)
                    mma_f16(acc[mi][ni], af[cur][mi][0], af[cur][mi][1],
                            af[cur][mi][2], af[cur][mi][3],
                            bf[cur][ni >> 1][(ni & 1)*2], bf[cur][ni >> 1][(ni & 1)*2 + 1]);
        }
    }

    __syncthreads();
    int g = lane >> 2, t4 = lane & 3;
    #pragma unroll
    for (int mi = 0; mi < 2; mi++) {
        #pragma unroll
        for (int ni = 0; ni < 8; ni++) {
            int r0 = rowBlk + wm*32 + mi*16 + g;
            int c0 = colBlk + wn*64 + ni*8 + 2*t4;
            float v0 = acc[mi][ni][0], v1 = acc[mi][ni][1];
            float v2 = acc[mi][ni][2], v3 = acc[mi][ni][3];
            if (EPI >= 2) {
                float b0 = bias[c0], b1 = bias[c0+1];
                v0 += b0; v1 += b1; v2 += b0; v3 += b1;
            }
            if (EPI == 2) {
                v0 = gelu_exact(v0); v1 = gelu_exact(v1);
                v2 = gelu_exact(v2); v3 = gelu_exact(v3);
            }
            if (EPI == 3) {
                const float2 ra = *(const float2*)&resid[(long)r0*ldc + c0];
                const float2 rb = *(const float2*)&resid[(long)(r0+8)*ldc + c0];
                v0 += ra.x; v1 += ra.y; v2 += rb.x; v3 += rb.y;
            }
            if (EPI == 2) {
                *(__half2*)&((__half*)C)[(long)r0*ldc + c0]     = __floats2half2_rn(v0, v1);
                *(__half2*)&((__half*)C)[(long)(r0+8)*ldc + c0] = __floats2half2_rn(v2, v3);
            } else {
                *(float2*)&((float*)C)[(long)r0*ldc + c0]     = make_float2(v0, v1);
                *(float2*)&((float*)C)[(long)(r0+8)*ldc + c0] = make_float2(v2, v3);
            }
        }
    }
}

// ---------------- transpose fp32 -> fp16 ----------------
__global__ void transpose_h(const float* __restrict__ src, __half* __restrict__ dst,
                            int R, int Ccol)
{
    __shared__ float t[32][33];
    int c0 = blockIdx.x * 32, r0 = blockIdx.y * 32;
    int x = c0 + threadIdx.x;
    #pragma unroll
    for (int j = threadIdx.y; j < 32; j += 8)
        t[j][threadIdx.x] = src[(long)(r0 + j) * Ccol + x];
    __syncthreads();
    int x2 = r0 + threadIdx.x;
    #pragma unroll
    for (int j = threadIdx.y; j < 32; j += 8)
        dst[(long)(c0 + j) * R + x2] = __float2half_rn(t[threadIdx.x][j]);
}

// ---------------- fused conv QKV, 4-position register blocking ----------------
__global__ void __launch_bounds__(256, 2) conv_qkv(const float* __restrict__ x,
                                                   const float* __restrict__ qw,
                                                   const float* __restrict__ kw,
                                                   const float* __restrict__ vw)
{
    __shared__ float sp[3][P_+2][P_+2];
    __shared__ float swq[81], swk[81], swv[81];
    int tid = threadIdx.x;
    int patch = blockIdx.x;
    int b = patch >> 8;
    int n = patch & 255;
    const float* xp = x + (long)patch * C_;

    if (tid < 81) { swq[tid] = qw[tid]; swk[tid] = kw[tid]; swv[tid] = vw[tid]; }
    for (int i = tid; i < 3*(P_+2)*(P_+2); i += 256)
        ((float*)sp)[i] = 0.0f;
    __syncthreads();
    for (int i = tid; i < C_; i += 256) {
        int ch = i >> 10;
        int s  = i & 1023;
        sp[ch][(s >> 5)+1][(s & 31)+1] = xp[i];
    }
    __syncthreads();

    int pos0 = tid * 4;
    int yy = pos0 >> 5, xx = pos0 & 31;
    float aq[3][4], ak[3][4], av[3][4];
    #pragma unroll
    for (int o = 0; o < 3; o++)
        #pragma unroll
        for (int p = 0; p < 4; p++) { aq[o][p] = 0.f; ak[o][p] = 0.f; av[o][p] = 0.f; }

    #pragma unroll
    for (int i = 0; i < 3; i++) {
        #pragma unroll
        for (int dy = 0; dy < 3; dy++) {
            float r[6];
            #pragma unroll
            for (int t = 0; t < 6; t++) r[t] = sp[i][yy+dy][xx+t];
            #pragma unroll
            for (int dx = 0; dx < 3; dx++) {
                int wi = i*9 + dy*3 + dx;
                float wq0 = swq[wi], wq1 = swq[27+wi], wq2 = swq[54+wi];
                float wk0 = swk[wi], wk1 = swk[27+wi], wk2 = swk[54+wi];
                float wv0 = swv[wi], wv1 = swv[27+wi], wv2 = swv[54+wi];
                #pragma unroll
                for (int p = 0; p < 4; p++) {
                    float val = r[dx + p];
                    aq[0][p] = fmaf(val, wq0, aq[0][p]);
                    aq[1][p] = fmaf(val, wq1, aq[1][p]);
                    aq[2][p] = fmaf(val, wq2, aq[2][p]);
                    ak[0][p] = fmaf(val, wk0, ak[0][p]);
                    ak[1][p] = fmaf(val, wk1, ak[1][p]);
                    ak[2][p] = fmaf(val, wk2, ak[2][p]);
                    av[0][p] = fmaf(val, wv0, av[0][p]);
                    av[1][p] = fmaf(val, wv1, av[1][p]);
                    av[2][p] = fmaf(val, wv2, av[2][p]);
                }
            }
        }
    }

    #pragma unroll
    for (int o = 0; o < 3; o++) {
        int c0 = o*1024 + pos0;
        int h = c0 / HD_;
        int d = c0 - h*HD_;
        long bh = (long)(b*H_ + h);
        long base = (bh*N_ + n)*HD_ + d;
        *(__half2*)&g_hq[base]   = __floats2half2_rn(aq[o][0], aq[o][1]);
        *(__half2*)&g_hq[base+2] = __floats2half2_rn(aq[o][2], aq[o][3]);
        *(__half2*)&g_hk[base]   = __floats2half2_rn(ak[o][0], ak[o][1]);
        *(__half2*)&g_hk[base+2] = __floats2half2_rn(ak[o][2], ak[o][3]);
        #pragma unroll
        for (int p = 0; p < 4; p++)
            g_hvt[(bh*HD_ + d + p)*N_ + n] = __float2half_rn(av[o][p]);
    }
}

// ---------------- fused softmax + re-attention + BN -> fp16 ----------------
__global__ void __launch_bounds__(256) softmax_reatten(
    const float* __restrict__ attn, __half* __restrict__ attn2,
    const float* __restrict__ w,  const float* __restrict__ rb,
    const float* __restrict__ g,  const float* __restrict__ bta,
    const float* __restrict__ mean, const float* __restrict__ var)
{
    __shared__ float sp[8][256];
    __shared__ float sw[64], sscale[8], sshift[8];
    int tid = threadIdx.x;
    int h = tid >> 5, lane = tid & 31;
    if (tid < 64) sw[tid] = w[tid];
    if (tid < 8) {
        float inv = rsqrtf(var[tid] + 1e-5f);
        float gi = g[tid] * inv;
        sscale[tid] = gi;
        sshift[tid] = bta[tid] + (rb[tid] - mean[tid]) * gi;
    }
    int b = blockIdx.x >> 8, n = blockIdx.x & 255;
    const float scale = 0.051031036307982884f;
    const float* row = attn + (((long)(b*H_ + h))*N_ + n)*N_;

    float v[8];
    #pragma unroll
    for (int j = 0; j < 8; j++) v[j] = row[lane + j*32] * scale;
    float m = v[0];
    #pragma unroll
    for (int j = 1; j < 8; j++) m = fmaxf(m, v[j]);
    #pragma unroll
    for (int o = 16; o > 0; o >>= 1) m = fmaxf(m, __shfl_xor_sync(0xffffffffu, m, o));
    float s = 0.0f;
    float e[8];
    #pragma unroll
    for (int j = 0; j < 8; j++) { e[j] = __expf(v[j] - m); s += e[j]; }
    #pragma unroll
    for (int o = 16; o > 0; o >>= 1) s += __shfl_xor_sync(0xffffffffu, s, o);
    float inv = 1.0f / s;
    #pragma unroll
    for (int j = 0; j < 8; j++) sp[h][lane + j*32] = e[j] * inv;
    __syncthreads();

    float in[8];
    #pragma unroll
    for (int i = 0; i < 8; i++) in[i] = sp[i][tid];
    #pragma unroll
    for (int o = 0; o < 8; o++) {
        float acc = 0.0f;
        #pragma unroll
        for (int i = 0; i < 8; i++) acc = fmaf(sw[o*8 + i], in[i], acc);
        attn2[(((long)(b*H_ + o))*N_ + n)*N_ + tid] =
            __float2half_rn(acc * sscale[o] + sshift[o]);
    }
}

// ---------------- LayerNorm: two-level stats ----------------
__global__ void ln_part(const float* __restrict__ y)
{
    __shared__ double rs[8], rq[8];
    int b = blockIdx.y, seg = blockIdx.x;
    const float* p = y + (long)b * NC_ + (long)seg * (NC_/32);
    double s = 0.0, q = 0.0;
    for (int i = threadIdx.x; i < NC_/32; i += 256) {
        double v = (double)p[i];
        s += v; q += v * v;
    }
    #pragma unroll
    for (int o = 16; o > 0; o >>= 1) {
        s += __shfl_xor_sync(0xffffffffu, s, o);
        q += __shfl_xor_sync(0xffffffffu, q, o);
    }
    int lane = threadIdx.x & 31, wid = threadIdx.x >> 5;
    if (lane == 0) { rs[wid] = s; rq[wid] = q; }
    __syncthreads();
    if (threadIdx.x == 0) {
        double S = 0.0, Q = 0.0;
        #pragma unroll
        for (int i = 0; i < 8; i++) { S += rs[i]; Q += rq[i]; }
        g_part[(b*32 + seg)*2]     = S;
        g_part[(b*32 + seg)*2 + 1] = Q;
    }
}

__global__ void ln_fin(float* __restrict__ stats)
{
    int b = blockIdx.x, t = threadIdx.x;
    double s = g_part[(b*32 + t)*2];
    double q = g_part[(b*32 + t)*2 + 1];
    #pragma unroll
    for (int o = 16; o > 0; o >>= 1) {
        s += __shfl_xor_sync(0xffffffffu, s, o);
        q += __shfl_xor_sync(0xffffffffu, q, o);
    }
    if (t == 0) {
        double mu  = s / (double)NC_;
        double var = q / (double)NC_ - mu * mu;
        stats[b*2]   = (float)mu;
        stats[b*2+1] = (float)rsqrt(var + 1e-5);
    }
}

__global__ void ln_apply_dual(const float* __restrict__ y, const float* __restrict__ stats,
                              const float* __restrict__ g, const float* __restrict__ beta,
                              float* __restrict__ outf, __half* __restrict__ outh)
{
    long i = (long)blockIdx.x * blockDim.x + threadIdx.x;
    int b = (int)(i / NC_);
    int r = (int)(i % NC_);
    float v = (y[i] - stats[b*2]) * stats[b*2+1] * g[r] + beta[r];
    outf[i] = v;
    outh[i] = __float2half_rn(v);
}

__global__ void ln_apply(const float* __restrict__ y, const float* __restrict__ stats,
                         const float* __restrict__ g, const float* __restrict__ beta,
                         float* __restrict__ out)
{
    long i = (long)blockIdx.x * blockDim.x + threadIdx.x;
    int b = (int)(i / NC_);
    int r = (int)(i % NC_);
    out[i] = (y[i] - stats[b*2]) * stats[b*2+1] * g[r] + beta[r];
}

// ---------------- launch ----------------
extern "C" void kernel_launch(void* const* d_in, const int* in_sizes, int n_in,
                              void* d_out, int out_size)
{
    const float* x        = (const float*)d_in[0];
    const float* qconv_w  = (const float*)d_in[1];
    const float* kconv_w  = (const float*)d_in[2];
    const float* vconv_w  = (const float*)d_in[3];
    const float* reat_w   = (const float*)d_in[4];
    const float* reat_b   = (const float*)d_in[5];
    const float* bn_gamma = (const float*)d_in[6];
    const float* bn_beta  = (const float*)d_in[7];
    const float* bn_mean  = (const float*)d_in[8];
    const float* bn_var   = (const float*)d_in[9];
    const float* proj_w   = (const float*)d_in[10];
    const float* proj_b   = (const float*)d_in[11];
    const float* ln_g     = (const float*)d_in[12];
    const float* ln_b     = (const float*)d_in[13];
    const float* ff_w1    = (const float*)d_in[14];
    const float* ff_b1    = (const float*)d_in[15];
    const float* ff_w2    = (const float*)d_in[16];
    const float* ff_b2    = (const float*)d_in[17];
    float* out = (float*)d_out;

    __half *pq, *pk, *pvt, *pattn2, *pctx, *pynh, *ph, *pprojT, *pw1T, *pw2T;
    float *pattn, *py1, *pyn, *py2, *pstats;
    cudaGetSymbolAddress((void**)&pq,     g_hq);
    cudaGetSymbolAddress((void**)&pk,     g_hk);
    cudaGetSymbolAddress((void**)&pvt,    g_hvt);
    cudaGetSymbolAddress((void**)&pattn2, g_hattn2);
    cudaGetSymbolAddress((void**)&pctx,   g_hctx);
    cudaGetSymbolAddress((void**)&pynh,   g_hynh);
    cudaGetSymbolAddress((void**)&ph,     g_hh);
    cudaGetSymbolAddress((void**)&pprojT, g_hprojT);
    cudaGetSymbolAddress((void**)&pw1T,   g_hw1T);
    cudaGetSymbolAddress((void**)&pw2T,   g_hw2T);
    cudaGetSymbolAddress((void**)&pattn,  g_attn);
    cudaGetSymbolAddress((void**)&py1,    g_y1);
    cudaGetSymbolAddress((void**)&pyn,    g_yn);
    cudaGetSymbolAddress((void**)&py2,    g_y2);
    cudaGetSymbolAddress((void**)&pstats, g_stats);

    cudaFuncSetAttribute(hgemm<0,__half>,    cudaFuncAttributeMaxDynamicSharedMemorySize, HSMEM);
    cudaFuncSetAttribute(hgemm256<1,float>,  cudaFuncAttributeMaxDynamicSharedMemorySize, SMEM2);
    cudaFuncSetAttribute(hgemm192<2,__half>, cudaFuncAttributeMaxDynamicSharedMemorySize, SMEM4);
    cudaFuncSetAttribute(hgemm192<3,float>,  cudaFuncAttributeMaxDynamicSharedMemorySize, SMEM4);

    // 1. fused conv QKV  (launch 0)
    conv_qkv<<<B_*N_, 256>>>(x, qconv_w, kconv_w, vconv_w);

    // 2. S = Q K^T  (launch 1)
    hgemm256<1,float><<<dim3(1,2,BH_), 512, SMEM2>>>(pq, pk, pattn,
        HD_, HD_, HD_, N_, (long)N_*HD_, (long)N_*HD_, 1, 65536L, 0L, nullptr, nullptr);

    // 3. fused softmax + re-attention (launch 2)
    softmax_reatten<<<B_*N_, 256>>>(pattn, pattn2, reat_w, reat_b,
                                    bn_gamma, bn_beta, bn_mean, bn_var);

    // 4. ctx = attn2 @ V (launch 3)
    hgemm<0,__half><<<dim3(3,2,BH_), 256, HSMEM>>>(pattn2, pvt, pctx,
        N_, N_, N_, C_, 65536L, (long)HD_*N_, H_, (long)N_*C_, (long)HD_, nullptr, nullptr);

    // 5. proj weight transpose (launch 4)
    {
        dim3 blk(32, 8);
        transpose_h<<<dim3(C_/32, C_/32), blk>>>(proj_w, pprojT, C_, C_);
    }

    // 6. y1 = x + ctx @ proj_w + proj_b  (launch 5 — ncu target)
    // K=C, lda=C (ctx), ldb=C (projT rows K-contig, stride C), ldc=C. grid 16x16=256 CTAs
    hgemm192<3,float><<<dim3(C_/192, (B_*N_)/128), 384, SMEM4>>>(pctx, pprojT, py1,
        C_, C_, C_, C_, proj_b, x);

    // 7. FFN weight transposes
    {
        dim3 blk(32, 8);
        transpose_h<<<dim3(FF_/32, C_/32), blk>>>(ff_w1, pw1T, C_, FF_);
        transpose_h<<<dim3(C_/32, FF_/32), blk>>>(ff_w2, pw2T, FF_, C_);
    }

    // 8. LN1
    ln_part<<<dim3(32, B_), 256>>>(py1);
    ln_fin<<<B_, 32>>>(pstats);
    ln_apply_dual<<<QKV_SZ/256, 256>>>(py1, pstats, ln_g, ln_b, pyn, pynh);

    // 9. h = gelu(yn @ ff_w1 + b1)  — K=C, lda=C, ldb=C (w1T stride C), ldc=FF. grid 64x16=1024
    hgemm192<2,__half><<<dim3(FF_/192, (B_*N_)/128), 384, SMEM4>>>(pynh, pw1T, ph,
        C_, C_, C_, FF_, ff_b1, nullptr);

    // 10. y2 = yn + h @ ff_w2 + b2 — K=FF, lda=FF, ldb=FF (w2T stride FF), ldc=C. grid 16x16
    hgemm192<3,float><<<dim3(C_/192, (B_*N_)/128), 384, SMEM4>>>(ph, pw2T, py2,
        FF_, FF_, FF_, C_, ff_b2, pyn);

    // 11. LN2 -> out
    ln_part<<<dim3(32, B_), 256>>>(py2);
    ln_fin<<<B_, 32>>>(pstats);
    ln_apply<<<QKV_SZ/256, 256>>>(py2, pstats, ln_g, ln_b, out);
}

// round 11
// speedup vs baseline: 2.8652x; 1.0107x over previous
#include <cuda_runtime.h>
#include <cuda_fp16.h>
#include <math.h>
#include <stdint.h>

// ---------------- problem constants ----------------
#define B_   8
#define N_   256
#define C_   3072
#define H_   8
#define HD_  384
#define FF_  12288
#define P_   32
#define NC_  (N_*C_)
#define BH_  (B_*H_)
#define QKV_SZ   (B_*N_*C_)
#define ATT_SZ   (B_*H_*N_*N_)
#define HBUF_SZ  (B_*N_*FF_)

// ---------------- device scratch ----------------
__device__ __align__(256) __half g_hq[QKV_SZ];
__device__ __align__(256) __half g_hk[QKV_SZ];
__device__ __align__(256) __half g_hvt[QKV_SZ];     // V^T: (BH, hd, N)
__device__ __align__(256) __half g_hattn2[ATT_SZ];
__device__ __align__(256) __half g_hctx[QKV_SZ];
__device__ __align__(256) __half g_hynh[QKV_SZ];
__device__ __align__(256) __half g_hh[HBUF_SZ];
__device__ __align__(256) __half g_hprojT[C_*C_];
__device__ __align__(256) __half g_hw1T[(long)C_*FF_];
__device__ __align__(256) __half g_hw2T[(long)C_*FF_];
__device__ float g_attn[ATT_SZ];
__device__ float g_y1[QKV_SZ];
__device__ float g_yn[QKV_SZ];
__device__ float g_y2[QKV_SZ];
__device__ float g_stats[B_*2];
__device__ double g_part[B_*32*2];

// ---------------- helpers ----------------
__device__ __forceinline__ float gelu_exact(float x) {
    return 0.5f * x * (1.0f + erff(x * 0.70710678118654752f));
}
__device__ __forceinline__ uint32_t smem_u32(const void* p) {
    return (uint32_t)__cvta_generic_to_shared(p);
}
__device__ __forceinline__ void cpa16(uint32_t dst, const void* src) {
    asm volatile("cp.async.cg.shared.global [%0], [%1], 16;\n" :: "r"(dst), "l"(src));
}
__device__ __forceinline__ void cp_commit() { asm volatile("cp.async.commit_group;\n"); }
template<int NN> __device__ __forceinline__ void cp_wait() {
    asm volatile("cp.async.wait_group %0;\n" :: "n"(NN));
}
__device__ __forceinline__ void ldsm_x4(uint32_t* r, uint32_t addr) {
    asm volatile("ldmatrix.sync.aligned.m8n8.x4.shared.b16 {%0,%1,%2,%3}, [%4];"
                 : "=r"(r[0]), "=r"(r[1]), "=r"(r[2]), "=r"(r[3]) : "r"(addr));
}
__device__ __forceinline__ void mma_f16(float c[4], uint32_t a0, uint32_t a1, uint32_t a2,
                                        uint32_t a3, uint32_t b0, uint32_t b1) {
    asm volatile(
        "mma.sync.aligned.m16n8k16.row.col.f32.f16.f16.f32 "
        "{%0,%1,%2,%3},{%4,%5,%6,%7},{%8,%9},{%0,%1,%2,%3};\n"
        : "+f"(c[0]), "+f"(c[1]), "+f"(c[2]), "+f"(c[3])
        : "r"(a0), "r"(a1), "r"(a2), "r"(a3), "r"(b0), "r"(b1));
}

// ================= 128x256 fp16 GEMM, 512 threads, 4-stage (QK) =================
#define A2SZ (128*144)
#define B2SZ (256*144)
#define STG2 (A2SZ + B2SZ)    // 55296
#define SMEM2 (4*STG2)        // 221184

template<int EPI, typename OutT>
__global__ void __launch_bounds__(512, 1)
hgemm256(const __half* __restrict__ A, const __half* __restrict__ Bm, OutT* __restrict__ C,
         int K, int lda, int ldb, int ldc,
         long sA, long sB, int zdiv, long sC1, long sC2,
         const float* __restrict__ bias, const float* __restrict__ resid)
{
    extern __shared__ char smem[];
    const uint32_t sbase = smem_u32(smem);

    int tid = threadIdx.x;
    int warp = tid >> 5, lane = tid & 31;
    int wm = warp >> 2, wn = warp & 3;     // 4x4 warp grid, 32x64 warp tile
    int z = blockIdx.z;
    const __half* Ab = A + (long)z * sA;
    const __half* Bb = Bm + (long)z * sB;
    long coff = (long)(z / zdiv) * sC1 + (long)(z % zdiv) * sC2;
    OutT* Cb = C + coff;
    int rowBlk = blockIdx.y * 128;
    int colBlk = blockIdx.x * 256;

    float acc[2][8][4];
    #pragma unroll
    for (int mi = 0; mi < 2; mi++)
        #pragma unroll
        for (int ni = 0; ni < 8; ni++)
            #pragma unroll
            for (int r = 0; r < 4; r++) acc[mi][ni][r] = 0.0f;

    uint32_t aoff = (uint32_t)(((wm*32 + (lane & 15)) * 72 + ((lane >> 4) << 3)) * 2);
    uint32_t boff = (uint32_t)(((wn*64 + (lane & 7) + ((lane >> 4) << 3)) * 72 + (lane & 8)) * 2);

    auto load_chunk = [&](int ck, int s) {
        uint32_t ab = sbase + s*STG2;
        uint32_t bb = ab + A2SZ;
        const __half* Ag = Ab + (long)rowBlk * lda + ck*64;
        const __half* Bg = Bb + (long)colBlk * ldb + ck*64;
        #pragma unroll
        for (int it = 0; it < 2; it++) {
            int idx = tid + it*512;
            int row = idx >> 3, gq = idx & 7;
            cpa16(ab + row*144 + gq*16, Ag + (long)row*lda + gq*8);
        }
        #pragma unroll
        for (int it = 0; it < 4; it++) {
            int idx = tid + it*512;
            int row = idx >> 3, gq = idx & 7;
            cpa16(bb + row*144 + gq*16, Bg + (long)row*ldb + gq*8);
        }
        cp_commit();
    };

    int nc = K >> 6;
    load_chunk(0, 0);
    if (nc > 1) load_chunk(1, 1); else cp_commit();
    if (nc > 2) load_chunk(2, 2); else cp_commit();

    for (int c = 0; c < nc; c++) {
        cp_wait<2>();
        __syncthreads();
        if (c + 3 < nc) load_chunk(c + 3, (c + 3) & 3);
        else            cp_commit();

        uint32_t As = sbase + (c & 3)*STG2;
        uint32_t Bs = As + A2SZ;

        uint32_t af[2][2][4], bf[2][4][4];
        #pragma unroll
        for (int mi = 0; mi < 2; mi++) ldsm_x4(af[0][mi], As + aoff + mi*2304u);
        #pragma unroll
        for (int j = 0; j < 4; j++)    ldsm_x4(bf[0][j],  Bs + boff + j*2304u);

        #pragma unroll
        for (int ki = 0; ki < 4; ki++) {
            int cur = ki & 1;
            if (ki < 3) {
                int kk2 = (ki + 1) * 16 * 2;
                #pragma unroll
                for (int mi = 0; mi < 2; mi++) ldsm_x4(af[cur^1][mi], As + aoff + mi*2304u + kk2);
                #pragma unroll
                for (int j = 0; j < 4; j++)    ldsm_x4(bf[cur^1][j],  Bs + boff + j*2304u + kk2);
            }
            #pragma unroll
            for (int mi = 0; mi < 2; mi++)
                #pragma unroll
                for (int ni = 0; ni < 8; ni++)
                    mma_f16(acc[mi][ni], af[cur][mi][0], af[cur][mi][1],
                            af[cur][mi][2], af[cur][mi][3],
                            bf[cur][ni >> 1][(ni & 1)*2], bf[cur][ni >> 1][(ni & 1)*2 + 1]);
        }
    }

    __syncthreads();
    int g = lane >> 2, t4 = lane & 3;
    #pragma unroll
    for (int mi = 0; mi < 2; mi++) {
        #pragma unroll
        for (int ni = 0; ni < 8; ni++) {
            int r0 = rowBlk + wm*32 + mi*16 + g;
            int c0 = colBlk + wn*64 + ni*8 + 2*t4;
            float v0 = acc[mi][ni][0], v1 = acc[mi][ni][1];
            float v2 = acc[mi][ni][2], v3 = acc[mi][ni][3];
            if (EPI == 0 || EPI == 2) {
                *(__half2*)&((__half*)Cb)[(long)r0*ldc + c0]     = __floats2half2_rn(v0, v1);
                *(__half2*)&((__half*)Cb)[(long)(r0+8)*ldc + c0] = __floats2half2_rn(v2, v3);
            } else {
                *(float2*)&((float*)Cb)[(long)r0*ldc + c0]     = make_float2(v0, v1);
                *(float2*)&((float*)Cb)[(long)(r0+8)*ldc + c0] = make_float2(v2, v3);
            }
        }
    }
}

// ================= 128x192 fp16 GEMM, 384 threads, 4-stage (batched) =================
#define A4SZ (128*144)        // 18432
#define B4SZ (192*144)        // 27648
#define STG4 (A4SZ + B4SZ)    // 46080
#define SMEM4 (4*STG4)        // 184320

// EPI: 0 plain->half, 2 bias+gelu->half, 3 bias+resid->float
template<int EPI, typename OutT>
__global__ void __launch_bounds__(384, 1)
hgemm192(const __half* __restrict__ A, const __half* __restrict__ Bm, OutT* __restrict__ C,
         int K, int lda, int ldb, int ldc,
         long sA, long sB, int zdiv, long sC1, long sC2,
         const float* __restrict__ bias, const float* __restrict__ resid)
{
    extern __shared__ char smem[];
    const uint32_t sbase = smem_u32(smem);

    int tid = threadIdx.x;
    int warp = tid >> 5, lane = tid & 31;
    int wm = warp / 3, wn = warp % 3;      // 4x3 warp grid, 32x64 warp tile
    int z = blockIdx.z;
    const __half* Ab = A + (long)z * sA;
    const __half* Bb = Bm + (long)z * sB;
    long coff = (long)(z / zdiv) * sC1 + (long)(z % zdiv) * sC2;
    OutT* Cb = C + coff;
    int rowBlk = blockIdx.y * 128;
    int colBlk = blockIdx.x * 192;

    float acc[2][8][4];
    #pragma unroll
    for (int mi = 0; mi < 2; mi++)
        #pragma unroll
        for (int ni = 0; ni < 8; ni++)
            #pragma unroll
            for (int r = 0; r < 4; r++) acc[mi][ni][r] = 0.0f;

    uint32_t aoff = (uint32_t)(((wm*32 + (lane & 15)) * 72 + ((lane >> 4) << 3)) * 2);
    uint32_t boff = (uint32_t)(((wn*64 + (lane & 7) + ((lane >> 4) << 3)) * 72 + (lane & 8)) * 2);

    auto load_chunk = [&](int ck, int s) {
        uint32_t ab = sbase + s*STG4;
        uint32_t bb = ab + A4SZ;
        const __half* Ag = Ab + (long)rowBlk * lda + ck*64;
        const __half* Bg = Bb + (long)colBlk * ldb + ck*64;
        #pragma unroll
        for (int it = 0; it < 3; it++) {           // A: 1024 granules over 384 thr
            int idx = tid + it*384;
            if (idx < 1024) {
                int row = idx >> 3, gq = idx & 7;
                cpa16(ab + row*144 + gq*16, Ag + (long)row*lda + gq*8);
            }
        }
        #pragma unroll
        for (int it = 0; it < 4; it++) {           // B: 1536 granules = 4*384 exactly
            int idx = tid + it*384;
            int row = idx >> 3, gq = idx & 7;
            cpa16(bb + row*144 + gq*16, Bg + (long)row*ldb + gq*8);
        }
        cp_commit();
    };

    int nc = K >> 6;
    load_chunk(0, 0);
    if (nc > 1) load_chunk(1, 1); else cp_commit();
    if (nc > 2) load_chunk(2, 2); else cp_commit();

    for (int c = 0; c < nc; c++) {
        cp_wait<2>();
        __syncthreads();
        if (c + 3 < nc) load_chunk(c + 3, (c + 3) & 3);
        else            cp_commit();

        uint32_t As = sbase + (c & 3)*STG4;
        uint32_t Bs = As + A4SZ;

        uint32_t af[2][2][4], bf[2][4][4];
        #pragma unroll
        for (int mi = 0; mi < 2; mi++) ldsm_x4(af[0][mi], As + aoff + mi*2304u);
        #pragma unroll
        for (int j = 0; j < 4; j++)    ldsm_x4(bf[0][j],  Bs + boff + j*2304u);

        #pragma unroll
        for (int ki = 0; ki < 4; ki++) {
            int cur = ki & 1;
            if (ki < 3) {
                int kk2 = (ki + 1) * 32;
                #pragma unroll
                for (int mi = 0; mi < 2; mi++) ldsm_x4(af[cur^1][mi], As + aoff + mi*2304u + kk2);
                #pragma unroll
                for (int j = 0; j < 4; j++)    ldsm_x4(bf[cur^1][j],  Bs + boff + j*2304u + kk2);
            }
            #pragma unroll
            for (int mi = 0; mi < 2; mi++)
                #pragma unroll
                for (int ni = 0; ni < 8; ni++)
                    mma_f16(acc[mi][ni], af[cur][mi][0], af[cur][mi][1],
                            af[cur][mi][2], af[cur][mi][3],
                            bf[cur][ni >> 1][(ni & 1)*2], bf[cur][ni >> 1][(ni & 1)*2 + 1]);
        }
    }

    __syncthreads();
    int g = lane >> 2, t4 = lane & 3;
    #pragma unroll
    for (int mi = 0; mi < 2; mi++) {
        #pragma unroll
        for (int ni = 0; ni < 8; ni++) {
            int r0 = rowBlk + wm*32 + mi*16 + g;
            int c0 = colBlk + wn*64 + ni*8 + 2*t4;
            float v0 = acc[mi][ni][0], v1 = acc[mi][ni][1];
            float v2 = acc[mi][ni][2], v3 = acc[mi][ni][3];
            if (EPI >= 2) {
                float b0 = bias[c0], b1 = bias[c0+1];
                v0 += b0; v1 += b1; v2 += b0; v3 += b1;
            }
            if (EPI == 2) {
                v0 = gelu_exact(v0); v1 = gelu_exact(v1);
                v2 = gelu_exact(v2); v3 = gelu_exact(v3);
            }
            if (EPI == 3) {
                const float2 ra = *(const float2*)&resid[coff + (long)r0*ldc + c0];
                const float2 rb = *(const float2*)&resid[coff + (long)(r0+8)*ldc + c0];
                v0 += ra.x; v1 += ra.y; v2 += rb.x; v3 += rb.y;
            }
            if (EPI == 0 || EPI == 2) {
                *(__half2*)&((__half*)Cb)[(long)r0*ldc + c0]     = __floats2half2_rn(v0, v1);
                *(__half2*)&((__half*)Cb)[(long)(r0+8)*ldc + c0] = __floats2half2_rn(v2, v3);
            } else {
                *(float2*)&((float*)Cb)[(long)r0*ldc + c0]     = make_float2(v0, v1);
                *(float2*)&((float*)Cb)[(long)(r0+8)*ldc + c0] = make_float2(v2, v3);
            }
        }
    }
}

// ---------------- fast transpose fp32 -> fp16, half2 stores ----------------
// src [Rr][Ccol] row-major -> dst [Ccol][Rr]; processes 64(r) x 32(c) input tile.
__global__ void transpose_h2(const float* __restrict__ src, __half* __restrict__ dst,
                             int Rr, int Ccol)
{
    __shared__ float t[64][33];
    int c0 = blockIdx.x * 32, r0 = blockIdx.y * 64;
    int tx = threadIdx.x, ty = threadIdx.y;
    int x = c0 + tx;
    #pragma unroll
    for (int j = ty; j < 64; j += 8)
        t[j][tx] = src[(long)(r0 + j) * Ccol + x];
    __syncthreads();
    #pragma unroll
    for (int j = ty; j < 32; j += 8) {
        __half2 h = __floats2half2_rn(t[2*tx][j], t[2*tx+1][j]);
        *(__half2*)&dst[(long)(c0 + j) * Rr + r0 + 2*tx] = h;
    }
}

// ---------------- fused conv QKV, 4-position register blocking ----------------
__global__ void __launch_bounds__(256, 2) conv_qkv(const float* __restrict__ x,
                                                   const float* __restrict__ qw,
                                                   const float* __restrict__ kw,
                                                   const float* __restrict__ vw)
{
    __shared__ float sp[3][P_+2][P_+2];
    __shared__ float swq[81], swk[81], swv[81];
    int tid = threadIdx.x;
    int patch = blockIdx.x;
    int b = patch >> 8;
    int n = patch & 255;
    const float* xp = x + (long)patch * C_;

    if (tid < 81) { swq[tid] = qw[tid]; swk[tid] = kw[tid]; swv[tid] = vw[tid]; }
    for (int i = tid; i < 3*(P_+2)*(P_+2); i += 256)
        ((float*)sp)[i] = 0.0f;
    __syncthreads();
    for (int i = tid; i < C_; i += 256) {
        int ch = i >> 10;
        int s  = i & 1023;
        sp[ch][(s >> 5)+1][(s & 31)+1] = xp[i];
    }
    __syncthreads();

    int pos0 = tid * 4;
    int yy = pos0 >> 5, xx = pos0 & 31;
    float aq[3][4], ak[3][4], av[3][4];
    #pragma unroll
    for (int o = 0; o < 3; o++)
        #pragma unroll
        for (int p = 0; p < 4; p++) { aq[o][p] = 0.f; ak[o][p] = 0.f; av[o][p] = 0.f; }

    #pragma unroll
    for (int i = 0; i < 3; i++) {
        #pragma unroll
        for (int dy = 0; dy < 3; dy++) {
            float r[6];
            #pragma unroll
            for (int t = 0; t < 6; t++) r[t] = sp[i][yy+dy][xx+t];
            #pragma unroll
            for (int dx = 0; dx < 3; dx++) {
                int wi = i*9 + dy*3 + dx;
                float wq0 = swq[wi], wq1 = swq[27+wi], wq2 = swq[54+wi];
                float wk0 = swk[wi], wk1 = swk[27+wi], wk2 = swk[54+wi];
                float wv0 = swv[wi], wv1 = swv[27+wi], wv2 = swv[54+wi];
                #pragma unroll
                for (int p = 0; p < 4; p++) {
                    float val = r[dx + p];
                    aq[0][p] = fmaf(val, wq0, aq[0][p]);
                    aq[1][p] = fmaf(val, wq1, aq[1][p]);
                    aq[2][p] = fmaf(val, wq2, aq[2][p]);
                    ak[0][p] = fmaf(val, wk0, ak[0][p]);
                    ak[1][p] = fmaf(val, wk1, ak[1][p]);
                    ak[2][p] = fmaf(val, wk2, ak[2][p]);
                    av[0][p] = fmaf(val, wv0, av[0][p]);
                    av[1][p] = fmaf(val, wv1, av[1][p]);
                    av[2][p] = fmaf(val, wv2, av[2][p]);
                }
            }
        }
    }

    #pragma unroll
    for (int o = 0; o < 3; o++) {
        int c0 = o*1024 + pos0;
        int h = c0 / HD_;
        int d = c0 - h*HD_;
        long bh = (long)(b*H_ + h);
        long base = (bh*N_ + n)*HD_ + d;
        *(__half2*)&g_hq[base]   = __floats2half2_rn(aq[o][0], aq[o][1]);
        *(__half2*)&g_hq[base+2] = __floats2half2_rn(aq[o][2], aq[o][3]);
        *(__half2*)&g_hk[base]   = __floats2half2_rn(ak[o][0], ak[o][1]);
        *(__half2*)&g_hk[base+2] = __floats2half2_rn(ak[o][2], ak[o][3]);
        #pragma unroll
        for (int p = 0; p < 4; p++)
            g_hvt[(bh*HD_ + d + p)*N_ + n] = __float2half_rn(av[o][p]);
    }
}

// ---------------- fused softmax + re-attention + BN -> fp16 ----------------
__global__ void __launch_bounds__(256) softmax_reatten(
    const float* __restrict__ attn, __half* __restrict__ attn2,
    const float* __restrict__ w,  const float* __restrict__ rb,
    const float* __restrict__ g,  const float* __restrict__ bta,
    const float* __restrict__ mean, const float* __restrict__ var)
{
    __shared__ float sp[8][256];
    __shared__ float sw[64], sscale[8], sshift[8];
    int tid = threadIdx.x;
    int h = tid >> 5, lane = tid & 31;
    if (tid < 64) sw[tid] = w[tid];
    if (tid < 8) {
        float inv = rsqrtf(var[tid] + 1e-5f);
        float gi = g[tid] * inv;
        sscale[tid] = gi;
        sshift[tid] = bta[tid] + (rb[tid] - mean[tid]) * gi;
    }
    int b = blockIdx.x >> 8, n = blockIdx.x & 255;
    const float scale = 0.051031036307982884f;
    const float* row = attn + (((long)(b*H_ + h))*N_ + n)*N_;

    float v[8];
    #pragma unroll
    for (int j = 0; j < 8; j++) v[j] = row[lane + j*32] * scale;
    float m = v[0];
    #pragma unroll
    for (int j = 1; j < 8; j++) m = fmaxf(m, v[j]);
    #pragma unroll
    for (int o = 16; o > 0; o >>= 1) m = fmaxf(m, __shfl_xor_sync(0xffffffffu, m, o));
    float s = 0.0f;
    float e[8];
    #pragma unroll
    for (int j = 0; j < 8; j++) { e[j] = __expf(v[j] - m); s += e[j]; }
    #pragma unroll
    for (int o = 16; o > 0; o >>= 1) s += __shfl_xor_sync(0xffffffffu, s, o);
    float inv = 1.0f / s;
    #pragma unroll
    for (int j = 0; j < 8; j++) sp[h][lane + j*32] = e[j] * inv;
    __syncthreads();

    float in[8];
    #pragma unroll
    for (int i = 0; i < 8; i++) in[i] = sp[i][tid];
    #pragma unroll
    for (int o = 0; o < 8; o++) {
        float acc = 0.0f;
        #pragma unroll
        for (int i = 0; i < 8; i++) acc = fmaf(sw[o*8 + i], in[i], acc);
        attn2[(((long)(b*H_ + o))*N_ + n)*N_ + tid] =
            __float2half_rn(acc * sscale[o] + sshift[o]);
    }
}

// ---------------- LayerNorm: two-level stats ----------------
__global__ void ln_part(const float* __restrict__ y)
{
    __shared__ double rs[8], rq[8];
    int b = blockIdx.y, seg = blockIdx.x;
    const float* p = y + (long)b * NC_ + (long)seg * (NC_/32);
    double s = 0.0, q = 0.0;
    for (int i = threadIdx.x; i < NC_/32; i += 256) {
        double v = (double)p[i];
        s += v; q += v * v;
    }
    #pragma unroll
    for (int o = 16; o > 0; o >>= 1) {
        s += __shfl_xor_sync(0xffffffffu, s, o);
        q += __shfl_xor_sync(0xffffffffu, q, o);
    }
    int lane = threadIdx.x & 31, wid = threadIdx.x >> 5;
    if (lane == 0) { rs[wid] = s; rq[wid] = q; }
    __syncthreads();
    if (threadIdx.x == 0) {
        double S = 0.0, Q = 0.0;
        #pragma unroll
        for (int i = 0; i < 8; i++) { S += rs[i]; Q += rq[i]; }
        g_part[(b*32 + seg)*2]     = S;
        g_part[(b*32 + seg)*2 + 1] = Q;
    }
}

__global__ void ln_fin(float* __restrict__ stats)
{
    int b = blockIdx.x, t = threadIdx.x;
    double s = g_part[(b*32 + t)*2];
    double q = g_part[(b*32 + t)*2 + 1];
    #pragma unroll
    for (int o = 16; o > 0; o >>= 1) {
        s += __shfl_xor_sync(0xffffffffu, s, o);
        q += __shfl_xor_sync(0xffffffffu, q, o);
    }
    if (t == 0) {
        double mu  = s / (double)NC_;
        double var = q / (double)NC_ - mu * mu;
        stats[b*2]   = (float)mu;
        stats[b*2+1] = (float)rsqrt(var + 1e-5);
    }
}

__global__ void ln_apply_dual(const float* __restrict__ y, const float* __restrict__ stats,
                              const float* __restrict__ g, const float* __restrict__ beta,
                              float* __restrict__ outf, __half* __restrict__ outh)
{
    long i = (long)blockIdx.x * blockDim.x + threadIdx.x;
    int b = (int)(i / NC_);
    int r = (int)(i % NC_);
    float v = (y[i] - stats[b*2]) * stats[b*2+1] * g[r] + beta[r];
    outf[i] = v;
    outh[i] = __float2half_rn(v);
}

__global__ void ln_apply(const float* __restrict__ y, const float* __restrict__ stats,
                         const float* __restrict__ g, const float* __restrict__ beta,
                         float* __restrict__ out)
{
    long i = (long)blockIdx.x * blockDim.x + threadIdx.x;
    int b = (int)(i / NC_);
    int r = (int)(i % NC_);
    out[i] = (y[i] - stats[b*2]) * stats[b*2+1] * g[r] + beta[r];
}

// ---------------- launch ----------------
extern "C" void kernel_launch(void* const* d_in, const int* in_sizes, int n_in,
                              void* d_out, int out_size)
{
    const float* x        = (const float*)d_in[0];
    const float* qconv_w  = (const float*)d_in[1];
    const float* kconv_w  = (const float*)d_in[2];
    const float* vconv_w  = (const float*)d_in[3];
    const float* reat_w   = (const float*)d_in[4];
    const float* reat_b   = (const float*)d_in[5];
    const float* bn_gamma = (const float*)d_in[6];
    const float* bn_beta  = (const float*)d_in[7];
    const float* bn_mean  = (const float*)d_in[8];
    const float* bn_var   = (const float*)d_in[9];
    const float* proj_w   = (const float*)d_in[10];
    const float* proj_b   = (const float*)d_in[11];
    const float* ln_g     = (const float*)d_in[12];
    const float* ln_b     = (const float*)d_in[13];
    const float* ff_w1    = (const float*)d_in[14];
    const float* ff_b1    = (const float*)d_in[15];
    const float* ff_w2    = (const float*)d_in[16];
    const float* ff_b2    = (const float*)d_in[17];
    float* out = (float*)d_out;

    __half *pq, *pk, *pvt, *pattn2, *pctx, *pynh, *ph, *pprojT, *pw1T, *pw2T;
    float *pattn, *py1, *pyn, *py2, *pstats;
    cudaGetSymbolAddress((void**)&pq,     g_hq);
    cudaGetSymbolAddress((void**)&pk,     g_hk);
    cudaGetSymbolAddress((void**)&pvt,    g_hvt);
    cudaGetSymbolAddress((void**)&pattn2, g_hattn2);
    cudaGetSymbolAddress((void**)&pctx,   g_hctx);
    cudaGetSymbolAddress((void**)&pynh,   g_hynh);
    cudaGetSymbolAddress((void**)&ph,     g_hh);
    cudaGetSymbolAddress((void**)&pprojT, g_hprojT);
    cudaGetSymbolAddress((void**)&pw1T,   g_hw1T);
    cudaGetSymbolAddress((void**)&pw2T,   g_hw2T);
    cudaGetSymbolAddress((void**)&pattn,  g_attn);
    cudaGetSymbolAddress((void**)&py1,    g_y1);
    cudaGetSymbolAddress((void**)&pyn,    g_yn);
    cudaGetSymbolAddress((void**)&py2,    g_y2);
    cudaGetSymbolAddress((void**)&pstats, g_stats);

    cudaFuncSetAttribute(hgemm256<1,float>,  cudaFuncAttributeMaxDynamicSharedMemorySize, SMEM2);
    cudaFuncSetAttribute(hgemm192<0,__half>, cudaFuncAttributeMaxDynamicSharedMemorySize, SMEM4);
    cudaFuncSetAttribute(hgemm192<2,__half>, cudaFuncAttributeMaxDynamicSharedMemorySize, SMEM4);
    cudaFuncSetAttribute(hgemm192<3,float>,  cudaFuncAttributeMaxDynamicSharedMemorySize, SMEM4);

    // 1. fused conv QKV  (launch 0)
    conv_qkv<<<B_*N_, 256>>>(x, qconv_w, kconv_w, vconv_w);

    // 2. S = Q K^T  (launch 1)
    hgemm256<1,float><<<dim3(1,2,BH_), 512, SMEM2>>>(pq, pk, pattn,
        HD_, HD_, HD_, N_, (long)N_*HD_, (long)N_*HD_, 1, 65536L, 0L, nullptr, nullptr);

    // 3. fused softmax + re-attention (launch 2)
    softmax_reatten<<<B_*N_, 256>>>(pattn, pattn2, reat_w, reat_b,
                                    bn_gamma, bn_beta, bn_mean, bn_var);

    // 4. ctx = attn2 @ V (launch 3)  — per bh: M=256, N=384, K=256; B=vt rows stride N_
    hgemm192<0,__half><<<dim3(2,2,BH_), 384, SMEM4>>>(pattn2, pvt, pctx,
        N_, N_, N_, C_, 65536L, (long)HD_*N_, H_, (long)N_*C_, (long)HD_, nullptr, nullptr);

    // 5. proj weight transpose (launch 4)
    {
        dim3 blk(32, 8);
        transpose_h2<<<dim3(C_/32, C_/64), blk>>>(proj_w, pprojT, C_, C_);
    }

    // 6. y1 = x + ctx @ proj_w + proj_b  (launch 5 — ncu target)
    hgemm192<3,float><<<dim3(C_/192, (B_*N_)/128), 384, SMEM4>>>(pctx, pprojT, py1,
        C_, C_, C_, C_, 0L, 0L, 1, 0L, 0L, proj_b, x);

    // 7. FFN weight transposes
    {
        dim3 blk(32, 8);
        transpose_h2<<<dim3(FF_/32, C_/64), blk>>>(ff_w1, pw1T, C_, FF_);   // [C][FF] -> [FF][C]
        transpose_h2<<<dim3(C_/32, FF_/64), blk>>>(ff_w2, pw2T, FF_, C_);   // [FF][C] -> [C][FF]
    }

    // 8. LN1
    ln_part<<<dim3(32, B_), 256>>>(py1);
    ln_fin<<<B_, 32>>>(pstats);
    ln_apply_dual<<<QKV_SZ/256, 256>>>(py1, pstats, ln_g, ln_b, pyn, pynh);

    // 9. h = gelu(yn @ ff_w1 + b1)
    hgemm192<2,__half><<<dim3(FF_/192, (B_*N_)/128), 384, SMEM4>>>(pynh, pw1T, ph,
        C_, C_, C_, FF_, 0L, 0L, 1, 0L, 0L, ff_b1, nullptr);

    // 10. y2 = yn + h @ ff_w2 + b2
    hgemm192<3,float><<<dim3(C_/192, (B_*N_)/128), 384, SMEM4>>>(ph, pw2T, py2,
        FF_, FF_, FF_, C_, 0L, 0L, 1, 0L, 0L, ff_b2, pyn);

    // 11. LN2 -> out
    ln_part<<<dim3(32, B_), 256>>>(py2);
    ln_fin<<<B_, 32>>>(pstats);
    ln_apply<<<QKV_SZ/256, 256>>>(py2, pstats, ln_g, ln_b, out);
}